// round 15
// baseline (speedup 1.0000x reference)
#include <cuda_runtime.h>
#include <cuda_bf16.h>
#include <cstdint>

#define TDIM 512
#define IDIM 512
#define HDIM 1024
#define G4   4096
#define NBLK 128
#define STGA 0                 // staged h group A: [hi 32KB][lo 32KB]
#define STGB 65536             // staged h group B
#define DPA  131072            // partials A: 8 warps x 32m x 18 floats
#define DPB  (131072 + 18432)
#define SMEM2 167936
#define SMEM_G 65536

typedef unsigned long long ull;

__device__ float g_xg[(size_t)32 * TDIM * G4];
__device__ __align__(128) unsigned char g_W[(size_t)NBLK * 131072];
__device__ __align__(128) unsigned char g_hB[2][131072];
__device__ __align__(128) unsigned char g_AX[(size_t)128 * 16 * 16384];
__device__ __align__(128) unsigned char g_BW[(size_t)32 * 16 * 16384];
__device__ int g_cntA, g_cntB;

__device__ __forceinline__ int ld_acquire(const int* p) {
    int v; asm volatile("ld.global.acquire.gpu.b32 %0, [%1];" : "=r"(v) : "l"(p));
    return v;
}
__device__ __forceinline__ void red_release_add(int* p, int v) {
    asm volatile("red.release.gpu.global.add.s32 [%0], %1;" :: "l"(p), "r"(v) : "memory");
}
__device__ __forceinline__ void spin_ge(const int* p, int target) {
    while (ld_acquire(p) < target) { }
}
__device__ __forceinline__ void ldsm4(uint32_t a, uint32_t* r) {
    asm volatile("ldmatrix.sync.aligned.m8n8.x4.shared.b16 {%0,%1,%2,%3}, [%4];"
        : "=r"(r[0]), "=r"(r[1]), "=r"(r[2]), "=r"(r[3]) : "r"(a));
}
__device__ __forceinline__ void ldsm4t(uint32_t a, uint32_t* r) {
    asm volatile("ldmatrix.sync.aligned.m8n8.x4.trans.shared.b16 {%0,%1,%2,%3}, [%4];"
        : "=r"(r[0]), "=r"(r[1]), "=r"(r[2]), "=r"(r[3]) : "r"(a));
}
__device__ __forceinline__ void hmma(float* d, const uint32_t* a, const uint32_t* b) {
    asm volatile("mma.sync.aligned.m16n8k16.row.col.f32.bf16.bf16.f32 "
        "{%0,%1,%2,%3},{%4,%5,%6,%7},{%8,%9},{%0,%1,%2,%3};"
        : "+f"(d[0]), "+f"(d[1]), "+f"(d[2]), "+f"(d[3])
        : "r"(a[0]), "r"(a[1]), "r"(a[2]), "r"(a[3]), "r"(b[0]), "r"(b[1]));
}
__device__ __forceinline__ void cpa(uint32_t d, const void* s) {
    asm volatile("cp.async.cg.shared.global [%0], [%1], 16;" :: "r"(d), "l"(s) : "memory");
}
#define WAITG(N) asm volatile("cp.async.wait_group %0;" :: "n"(N) : "memory")
#define COMMIT() asm volatile("cp.async.commit_group;" ::: "memory")
__device__ __forceinline__ void split_bf16(float v, unsigned short& hi, unsigned short& lo) {
    __nv_bfloat16 h = __float2bfloat16(v);
    __nv_bfloat16 l = __float2bfloat16(v - __bfloat162float(h));
    hi = *(unsigned short*)&h; lo = *(unsigned short*)&l;
}
__device__ __forceinline__ float sigx(float x) {
    return __fdividef(1.0f, 1.0f + __expf(-x));
}
__device__ __forceinline__ float tanhx(float x) {
    return 2.0f * __fdividef(1.0f, 1.0f + __expf(-2.0f * x)) - 1.0f;
}

// ---- prep: Wh -> step-kernel A images --------------------------------------
__global__ void __launch_bounds__(256) prep_kernel(const float* __restrict__ Wh) {
    const int e = blockIdx.x * 256 + threadIdx.x;
    const int blk = e >> 14, rem = e & 16383;
    const int m = rem >> 9, k = (rem & 511) * 2;
    const int row = ((m >> 3) << 10) + (blk << 3) + (m & 7);
    const float2 wv = *(const float2*)(Wh + (size_t)row * HDIM + k);
    unsigned short h0, l0, h1, l1;
    split_bf16(wv.x, h0, l0); split_bf16(wv.y, h1, l1);
    const int mt = m >> 4, r = m & 15, kt = k >> 4, kc = k & 15;
    const uint32_t off = (uint32_t)(mt * 32768 + kt * 512 + r * 32
                       + (((kc >> 3) ^ ((r >> 2) & 1)) << 4) + (kc & 7) * 2);
    unsigned char* base = g_W + (size_t)blk * 131072;
    *(uint32_t*)(base + off)         = (uint32_t)h0 | ((uint32_t)h1 << 16);
    *(uint32_t*)(base + 65536 + off) = (uint32_t)l0 | ((uint32_t)l1 << 16);
    if (e < 32768) ((uint32_t*)g_hB[0])[e] = 0u;
    if (e == 0) { g_cntA = 0; g_cntB = 0; }
}

// ---- prep: X -> phase-1 A-images -------------------------------------------
__global__ void __launch_bounds__(256) prepA_kernel(const float* __restrict__ X) {
    const int e = blockIdx.x * 256 + threadIdx.x;
    const int k = (e & 255) * 2, m = e >> 8;
    const float2 xv = *(const float2*)(X + (size_t)m * IDIM + k);
    unsigned short h0, l0, h1, l1;
    split_bf16(xv.x, h0, l0); split_bf16(xv.y, h1, l1);
    const int R = m >> 7, rr = m & 127, mm = rr >> 4, r = rr & 15;
    const int kc = k >> 5, kt = (k >> 4) & 1, kcol = k & 15;
    unsigned char* base = g_AX + (size_t)(R * 16 + kc) * 16384 + kt * 8192 + mm * 512;
    const uint32_t off = (uint32_t)(r * 32 + (((kcol >> 3) ^ ((r >> 2) & 1)) << 4)
                       + (kcol & 7) * 2);
    *(uint32_t*)(base + off)        = (uint32_t)h0 | ((uint32_t)h1 << 16);
    *(uint32_t*)(base + 4096 + off) = (uint32_t)l0 | ((uint32_t)l1 << 16);
}

// ---- prep: Wx -> phase-1 B-images ------------------------------------------
__global__ void __launch_bounds__(256) prepB_kernel(const float* __restrict__ Wx) {
    const int e = blockIdx.x * 256 + threadIdx.x;
    const int k = e & 511, n = e >> 9;
    const float wv = Wx[(size_t)n * IDIM + k];
    unsigned short hi, lo; split_bf16(wv, hi, lo);
    const int NB = n >> 7, cc = n & 127, nt = cc >> 3, nn = cc & 7;
    const int kc = k >> 5, kt = (k >> 4) & 1, r = k & 15;
    unsigned char* base = g_BW + (size_t)(NB * 16 + kc) * 16384 + kt * 8192 + nt * 256;
    const uint32_t off = (uint32_t)(r * 16 + nn * 2);
    *(unsigned short*)(base + off)        = hi;
    *(unsigned short*)(base + 4096 + off) = lo;
}

// ---- Phase 1: HMMA GEMM, 2 CTAs/SM (proven, unchanged) ----------------------
__global__ void __launch_bounds__(256, 2) gemm_hmma_kernel(
    const float* __restrict__ bx, const float* __restrict__ bh)
{
    extern __shared__ unsigned char smc[];
    const uint32_t smb = (uint32_t)__cvta_generic_to_shared(smc);
    const int tid = threadIdx.x, lane = tid & 31, w = tid >> 5;
    const int mt = w & 3, nt = w >> 2;
    const int MB = blockIdx.y, NB = blockIdx.x;
    const unsigned char* srcA = g_AX + (size_t)MB * (16 * 16384);
    const unsigned char* srcB = g_BW + (size_t)NB * (16 * 16384);
    const int r = lane & 15, hb = lane >> 4;
    const uint32_t aSw = (uint32_t)(r * 32 + ((hb ^ ((r >> 2) & 1)) << 4));
    const uint32_t tb  = (uint32_t)(r * 16 + hb * 256);

    float acc[2][8][4];
#pragma unroll
    for (int i = 0; i < 2; i++)
#pragma unroll
        for (int j = 0; j < 8; j++)
#pragma unroll
            for (int q = 0; q < 4; q++) acc[i][j][q] = 0.0f;

#define LOADC(kc, s) { \
    _Pragma("unroll") for (int rd = 0; rd < 4; rd++) { \
        cpa(smb + (s) * 32768 + tid * 16 + rd * 4096, \
            srcA + (size_t)(kc) * 16384 + tid * 16 + rd * 4096); \
        cpa(smb + (s) * 32768 + 16384 + tid * 16 + rd * 4096, \
            srcB + (size_t)(kc) * 16384 + tid * 16 + rd * 4096); } \
    COMMIT(); }

    LOADC(0, 0)
    for (int kc = 0; kc < 16; kc++) {
        const int s = kc & 1;
        if (kc < 15) LOADC(kc + 1, 1 - s)
        if (kc < 15) { WAITG(1); } else { WAITG(0); }
        __syncthreads();
#pragma unroll
        for (int kt = 0; kt < 2; kt++) {
            const uint32_t ab = smb + s * 32768 + kt * 8192;
            const uint32_t bb = smb + s * 32768 + 16384 + kt * 8192 + tb;
            uint32_t Ah[2][4], Al[2][4];
#pragma unroll
            for (int i = 0; i < 2; i++) {
                ldsm4(ab + (2 * mt + i) * 512 + aSw, Ah[i]);
                ldsm4(ab + 4096 + (2 * mt + i) * 512 + aSw, Al[i]);
            }
#pragma unroll
            for (int jj = 0; jj < 4; jj++) {
                uint32_t Bh4[4], Bl4[4];
                ldsm4t(bb + (8 * nt + 2 * jj) * 256, Bh4);
                ldsm4t(bb + 4096 + (8 * nt + 2 * jj) * 256, Bl4);
#pragma unroll
                for (int sj = 0; sj < 2; sj++) {
                    const uint32_t* Bh = Bh4 + 2 * sj;
                    const uint32_t* Bl = Bl4 + 2 * sj;
#pragma unroll
                    for (int i = 0; i < 2; i++) {
                        hmma(acc[i][2 * jj + sj], Ah[i], Bh);
                        hmma(acc[i][2 * jj + sj], Al[i], Bh);
                        hmma(acc[i][2 * jj + sj], Ah[i], Bl);
                    }
                }
            }
        }
        __syncthreads();
    }
    const int g = lane >> 2, c2 = (lane & 3) << 1;
#pragma unroll
    for (int j = 0; j < 8; j++) {
        const int n0 = NB * 128 + nt * 64 + j * 8 + c2;
        const float2 bxv = *(const float2*)(bx + n0);
        const float2 bhv = *(const float2*)(bh + n0);
        const float b0 = bxv.x + bhv.x, b1 = bxv.y + bhv.y;
#pragma unroll
        for (int i = 0; i < 2; i++) {
            const int m0 = MB * 128 + mt * 32 + i * 16 + g;
            *(float2*)(g_xg + (size_t)m0 * G4 + n0) =
                make_float2(acc[i][j][0] + b0, acc[i][j][1] + b1);
            *(float2*)(g_xg + (size_t)(m0 + 8) * G4 + n0) =
                make_float2(acc[i][j][2] + b0, acc[i][j][3] + b1);
        }
    }
}

// ---- Phase 2: persistent HMMA recurrence, 2 pipelined batch groups ----------
__global__ void __launch_bounds__(256, 1) lstm_hmma_kernel(float* __restrict__ out)
{
    extern __shared__ unsigned char smc[];
    const uint32_t smb = (uint32_t)__cvta_generic_to_shared(smc);
    const int tid = threadIdx.x, lane = tid & 31, w = tid >> 5;
    const int r = lane & 15, hb = lane >> 4;

    // one-time: stage weight image into [0,128K), load A frags, then reuse smem
    {
        const unsigned char* src = g_W + (size_t)blockIdx.x * 131072;
#pragma unroll
        for (int cq = 0; cq < 32; cq++)
            cpa(smb + tid * 16 + cq * 4096, src + tid * 16 + cq * 4096);
        COMMIT();
        WAITG(0);
        __syncthreads();
    }
    uint32_t Ah[2][8][4], Al[2][8][4];
    {
        const uint32_t aSw = (uint32_t)(r * 32 + ((hb ^ ((r >> 2) & 1)) << 4));
#pragma unroll
        for (int mt = 0; mt < 2; mt++)
#pragma unroll
            for (int j = 0; j < 8; j++) {
                ldsm4(smb + mt * 32768 + (w * 8 + j) * 512 + aSw, Ah[mt][j]);
                ldsm4(smb + 65536 + mt * 32768 + (w * 8 + j) * 512 + aSw, Al[mt][j]);
            }
    }
    __syncthreads();

    float* DpA = (float*)(smc + DPA);
    float* DpB = (float*)(smc + DPB);
    const int cell = tid & 7;
    const int bloc = (tid >> 3) & 15;             // batch within group
    const int grp  = tid >> 7;                    // 0: A-epilogue, 1: B-epilogue
    const int bglb = grp * 16 + bloc;
    const int n = blockIdx.x * 8 + cell;
    const uint32_t tb = (uint32_t)(r * 16 + hb * 256);
    float cs = 0.0f;

    float xgv[4];
    {
        const float* xp = g_xg + ((size_t)bglb * TDIM) * G4 + n;
#pragma unroll
        for (int g2 = 0; g2 < 4; g2++) xgv[g2] = __ldg(xp + g2 * HDIM);
    }

    // stage macro: group chunk (0 = b0-15, 512 = b16-31), dst region
#define STAGE_GRP(DST, SRC, CHUNK) { \
    _Pragma("unroll") for (int j = 0; j < 8; j++) { \
        cpa(smb + (DST) + w * 4096 + j * 512 + lane * 16, \
            (SRC) + (w * 8 + j) * 1024 + (CHUNK) + lane * 16); \
        cpa(smb + (DST) + 32768 + w * 4096 + j * 512 + lane * 16, \
            (SRC) + 65536 + (w * 8 + j) * 1024 + (CHUNK) + lane * 16); } \
    COMMIT(); }

#define COMPUTE_GRP(STG, ACC) { \
    _Pragma("unroll") for (int j = 0; j < 8; j++) { \
        uint32_t Bh[4], Bl[4]; \
        const uint32_t jb = smb + (STG) + w * 4096 + j * 512 + tb; \
        ldsm4t(jb, Bh); \
        ldsm4t(jb + 32768, Bl); \
        _Pragma("unroll") for (int mt = 0; mt < 2; mt++) { \
            hmma(ACC[mt][0], Ah[mt][j], Bh); \
            hmma(ACC[mt][1], Ah[mt][j], Bh + 2); \
            hmma(ACC[mt][0], Al[mt][j], Bh); \
            hmma(ACC[mt][1], Al[mt][j], Bh + 2); \
            hmma(ACC[mt][0], Ah[mt][j], Bl); \
            hmma(ACC[mt][1], Ah[mt][j], Bl + 2); } } }

#define STORE_DP(DP, ACC) { \
    const int gg = lane >> 2, c2 = (lane & 3) << 1; \
    float* dpw = (DP) + w * 576; \
    _Pragma("unroll") for (int mt = 0; mt < 2; mt++) \
    _Pragma("unroll") for (int nt = 0; nt < 2; nt++) { \
        const int r0 = mt * 16 + gg, c0 = nt * 8 + c2; \
        *(float2*)(dpw + r0 * 18 + c0) = make_float2(ACC[mt][nt][0], ACC[mt][nt][1]); \
        *(float2*)(dpw + (r0 + 8) * 18 + c0) = make_float2(ACC[mt][nt][2], ACC[mt][nt][3]); } }

#define EPILOGUE(DP, HD, T) { \
    float s0 = xgv[0], s1 = xgv[1], s2 = xgv[2], s3 = xgv[3]; \
    _Pragma("unroll") for (int w2 = 0; w2 < 8; w2++) { \
        const float* dpw = (DP) + w2 * 576 + cell * 18 + bloc; \
        s0 += dpw[0]; s1 += dpw[8 * 18]; s2 += dpw[16 * 18]; s3 += dpw[24 * 18]; } \
    const float si = sigx(s0), sf = sigx(s1), so = sigx(s3); \
    cs = sf * cs + si * tanhx(s2); \
    const float h = so * tanhx(cs); \
    out[((size_t)bglb * TDIM + (T)) * HDIM + n] = h; \
    unsigned short hh, hl; split_bf16(h, hh, hl); \
    const uint32_t off = (uint32_t)((n >> 4) * 1024 + (bglb >> 3) * 256 \
                         + (n & 15) * 16 + (bglb & 7) * 2); \
    *(unsigned short*)((HD) + off)         = hh; \
    *(unsigned short*)((HD) + 65536 + off) = hl; \
    if ((T) + 1 < TDIM) { \
        const float* xp = g_xg + ((size_t)bglb * TDIM + (T) + 1) * G4 + n; \
        _Pragma("unroll") for (int g2 = 0; g2 < 4; g2++) xgv[g2] = __ldg(xp + g2 * HDIM); \
    } }

    // prologue: stage A(0)
    {
        const unsigned char* hsrc = g_hB[0];
        STAGE_GRP(STGA, hsrc, 0)
    }

    for (int t = 0; t < TDIM; t++) {
        const unsigned char* hsrc = g_hB[t & 1];
        unsigned char* hdst = g_hB[(t + 1) & 1];

        // stage B(t): gated on barB(t-1); hidden behind computeA
        spin_ge(&g_cntB, NBLK * t);
        STAGE_GRP(STGB, hsrc, 512)

        // compute group A
        WAITG(1); __syncwarp();
        float accA[2][2][4];
#pragma unroll
        for (int mt = 0; mt < 2; mt++)
#pragma unroll
            for (int nt = 0; nt < 2; nt++)
#pragma unroll
                for (int q = 0; q < 4; q++) accA[mt][nt][q] = 0.0f;
        COMPUTE_GRP(STGA, accA)
        STORE_DP(DpA, accA)
        __syncthreads();

        // epilogue A (warps 0-3) — warps 4-7 proceed straight to compute B
        if (tid < 128) {
            EPILOGUE(DpA, hdst, t)
            asm volatile("bar.sync 3, 128;" ::: "memory");
            if (tid == 0) red_release_add(&g_cntA, 1);
        }

        // compute group B
        WAITG(0); __syncwarp();
        float accB[2][2][4];
#pragma unroll
        for (int mt = 0; mt < 2; mt++)
#pragma unroll
            for (int nt = 0; nt < 2; nt++)
#pragma unroll
                for (int q = 0; q < 4; q++) accB[mt][nt][q] = 0.0f;
        COMPUTE_GRP(STGB, accB)

        // stage A(t+1): gated on barA(t); hidden behind partialsB + epiB
        if (t + 1 < TDIM) {
            spin_ge(&g_cntA, NBLK * (t + 1));
            STAGE_GRP(STGA, hdst, 0)
        }

        STORE_DP(DpB, accB)
        __syncthreads();

        // epilogue B (warps 4-7) — warps 0-3 loop around to stage B(t+1)
        if (tid >= 128) {
            EPILOGUE(DpB, hdst, t)
            asm volatile("bar.sync 4, 128;" ::: "memory");
            if (tid == 128) red_release_add(&g_cntB, 1);
        }
    }
}

// ---------------------------------------------------------------------------
extern "C" void kernel_launch(void* const* d_in, const int* in_sizes, int n_in,
                              void* d_out, int out_size)
{
    const float* x  = (const float*)d_in[0];
    const float* Wx = (const float*)d_in[1];
    const float* bx = (const float*)d_in[2];
    const float* Wh = (const float*)d_in[3];
    const float* bh = (const float*)d_in[4];
    float* out = (float*)d_out;
    (void)in_sizes; (void)n_in; (void)out_size;

    cudaFuncSetAttribute(lstm_hmma_kernel,
                         cudaFuncAttributeMaxDynamicSharedMemorySize, SMEM2);
    cudaFuncSetAttribute(gemm_hmma_kernel,
                         cudaFuncAttributeMaxDynamicSharedMemorySize, SMEM_G);

    prep_kernel<<<8192, 256>>>(Wh);
    prepA_kernel<<<16384, 256>>>(x);
    prepB_kernel<<<8192, 256>>>(Wx);

    dim3 ggrid(32, 128);
    gemm_hmma_kernel<<<ggrid, 256, SMEM_G>>>(bx, bh);

    lstm_hmma_kernel<<<NBLK, 256, SMEM2>>>(out);
}

// round 16
// speedup vs baseline: 1.2756x; 1.2756x over previous
#include <cuda_runtime.h>
#include <cuda_bf16.h>
#include <cstdint>

#define TDIM 512
#define IDIM 512
#define HDIM 1024
#define G4   4096
#define NBLK 128
#define HBH  0
#define HBL  65536
#define DPOFF 131072
#define SMEM2 165888
#define SMEM_G 65536

typedef unsigned long long ull;

__device__ float g_xg[(size_t)32 * TDIM * G4];
__device__ __align__(128) unsigned char g_W[(size_t)NBLK * 131072];
__device__ __align__(128) unsigned char g_hB[2][131072];
__device__ __align__(128) unsigned char g_AX[(size_t)128 * 16 * 16384];
__device__ __align__(128) unsigned char g_BW[(size_t)32 * 16 * 16384];
__device__ int g_count;

__device__ __forceinline__ int ld_acquire(const int* p) {
    int v; asm volatile("ld.global.acquire.gpu.b32 %0, [%1];" : "=r"(v) : "l"(p));
    return v;
}
__device__ __forceinline__ void red_release_add(int* p, int v) {
    asm volatile("red.release.gpu.global.add.s32 [%0], %1;" :: "l"(p), "r"(v) : "memory");
}
__device__ __forceinline__ void ldsm4(uint32_t a, uint32_t* r) {
    asm volatile("ldmatrix.sync.aligned.m8n8.x4.shared.b16 {%0,%1,%2,%3}, [%4];"
        : "=r"(r[0]), "=r"(r[1]), "=r"(r[2]), "=r"(r[3]) : "r"(a));
}
__device__ __forceinline__ void ldsm4t(uint32_t a, uint32_t* r) {
    asm volatile("ldmatrix.sync.aligned.m8n8.x4.trans.shared.b16 {%0,%1,%2,%3}, [%4];"
        : "=r"(r[0]), "=r"(r[1]), "=r"(r[2]), "=r"(r[3]) : "r"(a));
}
__device__ __forceinline__ void hmma(float* d, const uint32_t* a, const uint32_t* b) {
    asm volatile("mma.sync.aligned.m16n8k16.row.col.f32.bf16.bf16.f32 "
        "{%0,%1,%2,%3},{%4,%5,%6,%7},{%8,%9},{%0,%1,%2,%3};"
        : "+f"(d[0]), "+f"(d[1]), "+f"(d[2]), "+f"(d[3])
        : "r"(a[0]), "r"(a[1]), "r"(a[2]), "r"(a[3]), "r"(b[0]), "r"(b[1]));
}
__device__ __forceinline__ void cpa(uint32_t d, const void* s) {
    asm volatile("cp.async.cg.shared.global [%0], [%1], 16;" :: "r"(d), "l"(s) : "memory");
}
#define WAITG(N) asm volatile("cp.async.wait_group %0;" :: "n"(N) : "memory")
#define COMMIT() asm volatile("cp.async.commit_group;" ::: "memory")
__device__ __forceinline__ void split_bf16(float v, unsigned short& hi, unsigned short& lo) {
    __nv_bfloat16 h = __float2bfloat16(v);
    __nv_bfloat16 l = __float2bfloat16(v - __bfloat162float(h));
    hi = *(unsigned short*)&h; lo = *(unsigned short*)&l;
}
__device__ __forceinline__ float sigx(float x) {
    return __fdividef(1.0f, 1.0f + __expf(-x));
}
__device__ __forceinline__ float tanhx(float x) {
    return 2.0f * __fdividef(1.0f, 1.0f + __expf(-2.0f * x)) - 1.0f;
}

// ---- prep: Wh -> step-kernel A images --------------------------------------
__global__ void __launch_bounds__(256) prep_kernel(const float* __restrict__ Wh) {
    const int e = blockIdx.x * 256 + threadIdx.x;
    const int blk = e >> 14, rem = e & 16383;
    const int m = rem >> 9, k = (rem & 511) * 2;
    const int row = ((m >> 3) << 10) + (blk << 3) + (m & 7);
    const float2 wv = *(const float2*)(Wh + (size_t)row * HDIM + k);
    unsigned short h0, l0, h1, l1;
    split_bf16(wv.x, h0, l0); split_bf16(wv.y, h1, l1);
    const int mt = m >> 4, r = m & 15, kt = k >> 4, kc = k & 15;
    const uint32_t off = (uint32_t)(mt * 32768 + kt * 512 + r * 32
                       + (((kc >> 3) ^ ((r >> 2) & 1)) << 4) + (kc & 7) * 2);
    unsigned char* base = g_W + (size_t)blk * 131072;
    *(uint32_t*)(base + off)         = (uint32_t)h0 | ((uint32_t)h1 << 16);
    *(uint32_t*)(base + 65536 + off) = (uint32_t)l0 | ((uint32_t)l1 << 16);
    if (e < 32768) ((uint32_t*)g_hB[0])[e] = 0u;
    if (e == 0) g_count = 0;
}

// ---- prep: X -> phase-1 A-images -------------------------------------------
__global__ void __launch_bounds__(256) prepA_kernel(const float* __restrict__ X) {
    const int e = blockIdx.x * 256 + threadIdx.x;
    const int k = (e & 255) * 2, m = e >> 8;
    const float2 xv = *(const float2*)(X + (size_t)m * IDIM + k);
    unsigned short h0, l0, h1, l1;
    split_bf16(xv.x, h0, l0); split_bf16(xv.y, h1, l1);
    const int R = m >> 7, rr = m & 127, mm = rr >> 4, r = rr & 15;
    const int kc = k >> 5, kt = (k >> 4) & 1, kcol = k & 15;
    unsigned char* base = g_AX + (size_t)(R * 16 + kc) * 16384 + kt * 8192 + mm * 512;
    const uint32_t off = (uint32_t)(r * 32 + (((kcol >> 3) ^ ((r >> 2) & 1)) << 4)
                       + (kcol & 7) * 2);
    *(uint32_t*)(base + off)        = (uint32_t)h0 | ((uint32_t)h1 << 16);
    *(uint32_t*)(base + 4096 + off) = (uint32_t)l0 | ((uint32_t)l1 << 16);
}

// ---- prep: Wx -> phase-1 B-images ------------------------------------------
__global__ void __launch_bounds__(256) prepB_kernel(const float* __restrict__ Wx) {
    const int e = blockIdx.x * 256 + threadIdx.x;
    const int k = e & 511, n = e >> 9;
    const float wv = Wx[(size_t)n * IDIM + k];
    unsigned short hi, lo; split_bf16(wv, hi, lo);
    const int NB = n >> 7, cc = n & 127, nt = cc >> 3, nn = cc & 7;
    const int kc = k >> 5, kt = (k >> 4) & 1, r = k & 15;
    unsigned char* base = g_BW + (size_t)(NB * 16 + kc) * 16384 + kt * 8192 + nt * 256;
    const uint32_t off = (uint32_t)(r * 16 + nn * 2);
    *(unsigned short*)(base + off)        = hi;
    *(unsigned short*)(base + 4096 + off) = lo;
}

// ---- Phase 1: HMMA GEMM, 2 CTAs/SM (proven, unchanged) ----------------------
__global__ void __launch_bounds__(256, 2) gemm_hmma_kernel(
    const float* __restrict__ bx, const float* __restrict__ bh)
{
    extern __shared__ unsigned char smc[];
    const uint32_t smb = (uint32_t)__cvta_generic_to_shared(smc);
    const int tid = threadIdx.x, lane = tid & 31, w = tid >> 5;
    const int mt = w & 3, nt = w >> 2;
    const int MB = blockIdx.y, NB = blockIdx.x;
    const unsigned char* srcA = g_AX + (size_t)MB * (16 * 16384);
    const unsigned char* srcB = g_BW + (size_t)NB * (16 * 16384);
    const int r = lane & 15, hb = lane >> 4;
    const uint32_t aSw = (uint32_t)(r * 32 + ((hb ^ ((r >> 2) & 1)) << 4));
    const uint32_t tb  = (uint32_t)(r * 16 + hb * 256);

    float acc[2][8][4];
#pragma unroll
    for (int i = 0; i < 2; i++)
#pragma unroll
        for (int j = 0; j < 8; j++)
#pragma unroll
            for (int q = 0; q < 4; q++) acc[i][j][q] = 0.0f;

#define LOADC(kc, s) { \
    _Pragma("unroll") for (int rd = 0; rd < 4; rd++) { \
        cpa(smb + (s) * 32768 + tid * 16 + rd * 4096, \
            srcA + (size_t)(kc) * 16384 + tid * 16 + rd * 4096); \
        cpa(smb + (s) * 32768 + 16384 + tid * 16 + rd * 4096, \
            srcB + (size_t)(kc) * 16384 + tid * 16 + rd * 4096); } \
    COMMIT(); }

    LOADC(0, 0)
    for (int kc = 0; kc < 16; kc++) {
        const int s = kc & 1;
        if (kc < 15) LOADC(kc + 1, 1 - s)
        if (kc < 15) { WAITG(1); } else { WAITG(0); }
        __syncthreads();
#pragma unroll
        for (int kt = 0; kt < 2; kt++) {
            const uint32_t ab = smb + s * 32768 + kt * 8192;
            const uint32_t bb = smb + s * 32768 + 16384 + kt * 8192 + tb;
            uint32_t Ah[2][4], Al[2][4];
#pragma unroll
            for (int i = 0; i < 2; i++) {
                ldsm4(ab + (2 * mt + i) * 512 + aSw, Ah[i]);
                ldsm4(ab + 4096 + (2 * mt + i) * 512 + aSw, Al[i]);
            }
#pragma unroll
            for (int jj = 0; jj < 4; jj++) {
                uint32_t Bh4[4], Bl4[4];
                ldsm4t(bb + (8 * nt + 2 * jj) * 256, Bh4);
                ldsm4t(bb + 4096 + (8 * nt + 2 * jj) * 256, Bl4);
#pragma unroll
                for (int sj = 0; sj < 2; sj++) {
                    const uint32_t* Bh = Bh4 + 2 * sj;
                    const uint32_t* Bl = Bl4 + 2 * sj;
#pragma unroll
                    for (int i = 0; i < 2; i++) {
                        hmma(acc[i][2 * jj + sj], Ah[i], Bh);
                        hmma(acc[i][2 * jj + sj], Al[i], Bh);
                        hmma(acc[i][2 * jj + sj], Ah[i], Bl);
                    }
                }
            }
        }
        __syncthreads();
    }
    const int g = lane >> 2, c2 = (lane & 3) << 1;
#pragma unroll
    for (int j = 0; j < 8; j++) {
        const int n0 = NB * 128 + nt * 64 + j * 8 + c2;
        const float2 bxv = *(const float2*)(bx + n0);
        const float2 bhv = *(const float2*)(bh + n0);
        const float b0 = bxv.x + bhv.x, b1 = bxv.y + bhv.y;
#pragma unroll
        for (int i = 0; i < 2; i++) {
            const int m0 = MB * 128 + mt * 32 + i * 16 + g;
            *(float2*)(g_xg + (size_t)m0 * G4 + n0) =
                make_float2(acc[i][j][0] + b0, acc[i][j][1] + b1);
            *(float2*)(g_xg + (size_t)(m0 + 8) * G4 + n0) =
                make_float2(acc[i][j][2] + b0, acc[i][j][3] + b1);
        }
    }
}

// ---- Phase 2: persistent HMMA recurrence (round-14 + split staging groups) --
__global__ void __launch_bounds__(256, 1) lstm_hmma_kernel(float* __restrict__ out)
{
    extern __shared__ unsigned char smc[];
    const uint32_t smb = (uint32_t)__cvta_generic_to_shared(smc);
    const int tid = threadIdx.x, lane = tid & 31, w = tid >> 5;
    const int r = lane & 15, hb = lane >> 4;

    {
        const unsigned char* src = g_W + (size_t)blockIdx.x * 131072;
#pragma unroll
        for (int cq = 0; cq < 32; cq++)
            cpa(smb + tid * 16 + cq * 4096, src + tid * 16 + cq * 4096);
        COMMIT();
        WAITG(0);
        __syncthreads();
    }
    uint32_t Ah[2][8][4], Al[2][8][4];
    {
        const uint32_t aSw = (uint32_t)(r * 32 + ((hb ^ ((r >> 2) & 1)) << 4));
#pragma unroll
        for (int mt = 0; mt < 2; mt++)
#pragma unroll
            for (int j = 0; j < 8; j++) {
                ldsm4(smb + mt * 32768 + (w * 8 + j) * 512 + aSw, Ah[mt][j]);
                ldsm4(smb + 65536 + mt * 32768 + (w * 8 + j) * 512 + aSw, Al[mt][j]);
            }
    }
    __syncthreads();

    float* Dp = (float*)(smc + DPOFF);
    const int cell = tid & 7, b = tid >> 3;
    const int n = blockIdx.x * 8 + cell;
    const uint32_t tb = (uint32_t)(r * 16 + hb * 256);
    float cs = 0.0f;

    float xgv[4];
    {
        const float* xp = g_xg + ((size_t)b * TDIM) * G4 + n;
#pragma unroll
        for (int g2 = 0; g2 < 4; g2++) xgv[g2] = __ldg(xp + g2 * HDIM);
    }

    for (int t = 0; t < TDIM; t++) {
        const unsigned char* hsrc = g_hB[t & 1];
        // per-warp staging, 4 commit groups of 4KB each (hi0,hi1,lo0,lo1)
        {
            const uint32_t dh = smb + HBH + w * 8192 + lane * 16;
            const uint32_t dl = smb + HBL + w * 8192 + lane * 16;
            const unsigned char* sh = hsrc + w * 8192 + lane * 16;
            const unsigned char* sl = hsrc + 65536 + w * 8192 + lane * 16;
#pragma unroll
            for (int q = 0; q < 8; q++)  cpa(dh + q * 512, sh + q * 512);
            COMMIT();
#pragma unroll
            for (int q = 8; q < 16; q++) cpa(dh + q * 512, sh + q * 512);
            COMMIT();
#pragma unroll
            for (int q = 0; q < 8; q++)  cpa(dl + q * 512, sl + q * 512);
            COMMIT();
#pragma unroll
            for (int q = 8; q < 16; q++) cpa(dl + q * 512, sl + q * 512);
            COMMIT();
        }

        float acc[2][4][4];
#pragma unroll
        for (int mt = 0; mt < 2; mt++)
#pragma unroll
            for (int nt = 0; nt < 4; nt++)
#pragma unroll
                for (int q = 0; q < 4; q++) acc[mt][nt][q] = 0.0f;

#define CSTEP(BASE, J, THREE)                                                  \
        {                                                                      \
            uint32_t B01[4], B23[4];                                           \
            const uint32_t jb = smb + (BASE) + (w * 8 + (J)) * 1024 + tb;      \
            ldsm4t(jb, B01);                                                   \
            ldsm4t(jb + 512, B23);                                             \
            _Pragma("unroll")                                                  \
            for (int mt = 0; mt < 2; mt++) {                                   \
                hmma(acc[mt][0], Ah[mt][J], B01);                              \
                hmma(acc[mt][1], Ah[mt][J], B01 + 2);                          \
                hmma(acc[mt][2], Ah[mt][J], B23);                              \
                hmma(acc[mt][3], Ah[mt][J], B23 + 2);                          \
                if (THREE) {                                                   \
                    hmma(acc[mt][0], Al[mt][J], B01);                          \
                    hmma(acc[mt][1], Al[mt][J], B01 + 2);                      \
                    hmma(acc[mt][2], Al[mt][J], B23);                          \
                    hmma(acc[mt][3], Al[mt][J], B23 + 2);                      \
                }                                                              \
            }                                                                  \
        }

        WAITG(3); __syncwarp();
#pragma unroll
        for (int j = 0; j < 4; j++) CSTEP(HBH, j, 1)
        WAITG(2); __syncwarp();
#pragma unroll
        for (int j = 4; j < 8; j++) CSTEP(HBH, j, 1)
        WAITG(1); __syncwarp();
#pragma unroll
        for (int j = 0; j < 4; j++) CSTEP(HBL, j, 0)
        WAITG(0); __syncwarp();
#pragma unroll
        for (int j = 4; j < 8; j++) CSTEP(HBL, j, 0)

        {
            const int g = lane >> 2, c2 = (lane & 3) << 1;
            float* dpw = Dp + w * 1088;
#pragma unroll
            for (int mt = 0; mt < 2; mt++)
#pragma unroll
                for (int nt = 0; nt < 4; nt++) {
                    const int r0 = mt * 16 + g, c0 = nt * 8 + c2;
                    *(float2*)(dpw + r0 * 34 + c0) =
                        make_float2(acc[mt][nt][0], acc[mt][nt][1]);
                    *(float2*)(dpw + (r0 + 8) * 34 + c0) =
                        make_float2(acc[mt][nt][2], acc[mt][nt][3]);
                }
        }
        __syncthreads();

        {
            float s0 = xgv[0], s1 = xgv[1], s2 = xgv[2], s3 = xgv[3];
#pragma unroll
            for (int w2 = 0; w2 < 8; w2++) {
                const float* dpw = Dp + w2 * 1088 + cell * 34 + b;
                s0 += dpw[0];
                s1 += dpw[8 * 34];
                s2 += dpw[16 * 34];
                s3 += dpw[24 * 34];
            }
            const float si = sigx(s0);
            const float sf = sigx(s1);
            const float so = sigx(s3);
            cs = sf * cs + si * tanhx(s2);
            const float h = so * tanhx(cs);
            out[((size_t)b * TDIM + t) * HDIM + n] = h;

            unsigned short hh, hl; split_bf16(h, hh, hl);
            unsigned char* hd = g_hB[(t + 1) & 1];
            const uint32_t off = (uint32_t)((n >> 4) * 1024 + (b >> 3) * 256
                                 + (n & 15) * 16 + (b & 7) * 2);
            *(unsigned short*)(hd + off)         = hh;
            *(unsigned short*)(hd + 65536 + off) = hl;
        }

        if (t < TDIM - 1) {
            __syncthreads();                          // all h stores done (CTA HB)
            if (tid == 0) red_release_add(&g_count, 1);
            {   // prefetch next xg during the spin shadow
                const float* xp = g_xg + ((size_t)b * TDIM + (t + 1)) * G4 + n;
#pragma unroll
                for (int g2 = 0; g2 < 4; g2++) xgv[g2] = __ldg(xp + g2 * HDIM);
            }
            // all-thread acquire spin (no trailing CTA barrier needed)
            while (ld_acquire(&g_count) < NBLK * (t + 1)) { }
        }
    }
}

// ---------------------------------------------------------------------------
extern "C" void kernel_launch(void* const* d_in, const int* in_sizes, int n_in,
                              void* d_out, int out_size)
{
    const float* x  = (const float*)d_in[0];
    const float* Wx = (const float*)d_in[1];
    const float* bx = (const float*)d_in[2];
    const float* Wh = (const float*)d_in[3];
    const float* bh = (const float*)d_in[4];
    float* out = (float*)d_out;
    (void)in_sizes; (void)n_in; (void)out_size;

    cudaFuncSetAttribute(lstm_hmma_kernel,
                         cudaFuncAttributeMaxDynamicSharedMemorySize, SMEM2);
    cudaFuncSetAttribute(gemm_hmma_kernel,
                         cudaFuncAttributeMaxDynamicSharedMemorySize, SMEM_G);

    prep_kernel<<<8192, 256>>>(Wh);
    prepA_kernel<<<16384, 256>>>(x);
    prepB_kernel<<<8192, 256>>>(Wx);

    dim3 ggrid(32, 128);
    gemm_hmma_kernel<<<ggrid, 256, SMEM_G>>>(bx, bh);

    lstm_hmma_kernel<<<NBLK, 256, SMEM2>>>(out);
}

// round 17
// speedup vs baseline: 1.3553x; 1.0625x over previous
#include <cuda_runtime.h>
#include <cuda_bf16.h>
#include <cstdint>

#define TDIM 512
#define IDIM 512
#define HDIM 1024
#define G4   4096
#define NBLK 128
#define HBH  0
#define HBL  65536
#define DPOFF 131072
#define SMEM2 165888
#define SMEM_G 65536

typedef unsigned long long ull;

__device__ float g_xg[(size_t)32 * TDIM * G4];
__device__ __align__(128) unsigned char g_W[(size_t)NBLK * 131072];
__device__ __align__(128) unsigned char g_hB[2][131072];
__device__ __align__(128) unsigned char g_AX[(size_t)128 * 16 * 16384];
__device__ __align__(128) unsigned char g_BW[(size_t)32 * 16 * 16384];
__device__ int g_flag[NBLK * 32];     // per-block release flag, 128B apart

__device__ __forceinline__ int ld_acquire(const int* p) {
    int v; asm volatile("ld.global.acquire.gpu.b32 %0, [%1];" : "=r"(v) : "l"(p));
    return v;
}
__device__ __forceinline__ void st_release(int* p, int v) {
    asm volatile("st.release.gpu.global.b32 [%0], %1;" :: "l"(p), "r"(v) : "memory");
}
__device__ __forceinline__ void ldsm4(uint32_t a, uint32_t* r) {
    asm volatile("ldmatrix.sync.aligned.m8n8.x4.shared.b16 {%0,%1,%2,%3}, [%4];"
        : "=r"(r[0]), "=r"(r[1]), "=r"(r[2]), "=r"(r[3]) : "r"(a));
}
__device__ __forceinline__ void ldsm4t(uint32_t a, uint32_t* r) {
    asm volatile("ldmatrix.sync.aligned.m8n8.x4.trans.shared.b16 {%0,%1,%2,%3}, [%4];"
        : "=r"(r[0]), "=r"(r[1]), "=r"(r[2]), "=r"(r[3]) : "r"(a));
}
__device__ __forceinline__ void hmma(float* d, const uint32_t* a, const uint32_t* b) {
    asm volatile("mma.sync.aligned.m16n8k16.row.col.f32.bf16.bf16.f32 "
        "{%0,%1,%2,%3},{%4,%5,%6,%7},{%8,%9},{%0,%1,%2,%3};"
        : "+f"(d[0]), "+f"(d[1]), "+f"(d[2]), "+f"(d[3])
        : "r"(a[0]), "r"(a[1]), "r"(a[2]), "r"(a[3]), "r"(b[0]), "r"(b[1]));
}
__device__ __forceinline__ void cpa(uint32_t d, const void* s) {
    asm volatile("cp.async.cg.shared.global [%0], [%1], 16;" :: "r"(d), "l"(s) : "memory");
}
#define WAITG(N) asm volatile("cp.async.wait_group %0;" :: "n"(N) : "memory")
#define COMMIT() asm volatile("cp.async.commit_group;" ::: "memory")
__device__ __forceinline__ void split_bf16(float v, unsigned short& hi, unsigned short& lo) {
    __nv_bfloat16 h = __float2bfloat16(v);
    __nv_bfloat16 l = __float2bfloat16(v - __bfloat162float(h));
    hi = *(unsigned short*)&h; lo = *(unsigned short*)&l;
}
__device__ __forceinline__ float sigx(float x) {
    return __fdividef(1.0f, 1.0f + __expf(-x));
}
__device__ __forceinline__ float tanhx(float x) {
    return 2.0f * __fdividef(1.0f, 1.0f + __expf(-2.0f * x)) - 1.0f;
}

// ---- prep: Wh -> step-kernel A images --------------------------------------
__global__ void __launch_bounds__(256) prep_kernel(const float* __restrict__ Wh) {
    const int e = blockIdx.x * 256 + threadIdx.x;
    const int blk = e >> 14, rem = e & 16383;
    const int m = rem >> 9, k = (rem & 511) * 2;
    const int row = ((m >> 3) << 10) + (blk << 3) + (m & 7);
    const float2 wv = *(const float2*)(Wh + (size_t)row * HDIM + k);
    unsigned short h0, l0, h1, l1;
    split_bf16(wv.x, h0, l0); split_bf16(wv.y, h1, l1);
    const int mt = m >> 4, r = m & 15, kt = k >> 4, kc = k & 15;
    const uint32_t off = (uint32_t)(mt * 32768 + kt * 512 + r * 32
                       + (((kc >> 3) ^ ((r >> 2) & 1)) << 4) + (kc & 7) * 2);
    unsigned char* base = g_W + (size_t)blk * 131072;
    *(uint32_t*)(base + off)         = (uint32_t)h0 | ((uint32_t)h1 << 16);
    *(uint32_t*)(base + 65536 + off) = (uint32_t)l0 | ((uint32_t)l1 << 16);
    if (e < 32768) ((uint32_t*)g_hB[0])[e] = 0u;
    if (e < NBLK) g_flag[e << 5] = 0;
}

// ---- prep: X -> phase-1 A-images -------------------------------------------
__global__ void __launch_bounds__(256) prepA_kernel(const float* __restrict__ X) {
    const int e = blockIdx.x * 256 + threadIdx.x;
    const int k = (e & 255) * 2, m = e >> 8;
    const float2 xv = *(const float2*)(X + (size_t)m * IDIM + k);
    unsigned short h0, l0, h1, l1;
    split_bf16(xv.x, h0, l0); split_bf16(xv.y, h1, l1);
    const int R = m >> 7, rr = m & 127, mm = rr >> 4, r = rr & 15;
    const int kc = k >> 5, kt = (k >> 4) & 1, kcol = k & 15;
    unsigned char* base = g_AX + (size_t)(R * 16 + kc) * 16384 + kt * 8192 + mm * 512;
    const uint32_t off = (uint32_t)(r * 32 + (((kcol >> 3) ^ ((r >> 2) & 1)) << 4)
                       + (kcol & 7) * 2);
    *(uint32_t*)(base + off)        = (uint32_t)h0 | ((uint32_t)h1 << 16);
    *(uint32_t*)(base + 4096 + off) = (uint32_t)l0 | ((uint32_t)l1 << 16);
}

// ---- prep: Wx -> phase-1 B-images ------------------------------------------
__global__ void __launch_bounds__(256) prepB_kernel(const float* __restrict__ Wx) {
    const int e = blockIdx.x * 256 + threadIdx.x;
    const int k = e & 511, n = e >> 9;
    const float wv = Wx[(size_t)n * IDIM + k];
    unsigned short hi, lo; split_bf16(wv, hi, lo);
    const int NB = n >> 7, cc = n & 127, nt = cc >> 3, nn = cc & 7;
    const int kc = k >> 5, kt = (k >> 4) & 1, r = k & 15;
    unsigned char* base = g_BW + (size_t)(NB * 16 + kc) * 16384 + kt * 8192 + nt * 256;
    const uint32_t off = (uint32_t)(r * 16 + nn * 2);
    *(unsigned short*)(base + off)        = hi;
    *(unsigned short*)(base + 4096 + off) = lo;
}

// ---- Phase 1: HMMA GEMM, 2 CTAs/SM (proven, unchanged) ----------------------
__global__ void __launch_bounds__(256, 2) gemm_hmma_kernel(
    const float* __restrict__ bx, const float* __restrict__ bh)
{
    extern __shared__ unsigned char smc[];
    const uint32_t smb = (uint32_t)__cvta_generic_to_shared(smc);
    const int tid = threadIdx.x, lane = tid & 31, w = tid >> 5;
    const int mt = w & 3, nt = w >> 2;
    const int MB = blockIdx.y, NB = blockIdx.x;
    const unsigned char* srcA = g_AX + (size_t)MB * (16 * 16384);
    const unsigned char* srcB = g_BW + (size_t)NB * (16 * 16384);
    const int r = lane & 15, hb = lane >> 4;
    const uint32_t aSw = (uint32_t)(r * 32 + ((hb ^ ((r >> 2) & 1)) << 4));
    const uint32_t tb  = (uint32_t)(r * 16 + hb * 256);

    float acc[2][8][4];
#pragma unroll
    for (int i = 0; i < 2; i++)
#pragma unroll
        for (int j = 0; j < 8; j++)
#pragma unroll
            for (int q = 0; q < 4; q++) acc[i][j][q] = 0.0f;

#define LOADC(kc, s) { \
    _Pragma("unroll") for (int rd = 0; rd < 4; rd++) { \
        cpa(smb + (s) * 32768 + tid * 16 + rd * 4096, \
            srcA + (size_t)(kc) * 16384 + tid * 16 + rd * 4096); \
        cpa(smb + (s) * 32768 + 16384 + tid * 16 + rd * 4096, \
            srcB + (size_t)(kc) * 16384 + tid * 16 + rd * 4096); } \
    COMMIT(); }

    LOADC(0, 0)
    for (int kc = 0; kc < 16; kc++) {
        const int s = kc & 1;
        if (kc < 15) LOADC(kc + 1, 1 - s)
        if (kc < 15) { WAITG(1); } else { WAITG(0); }
        __syncthreads();
#pragma unroll
        for (int kt = 0; kt < 2; kt++) {
            const uint32_t ab = smb + s * 32768 + kt * 8192;
            const uint32_t bb = smb + s * 32768 + 16384 + kt * 8192 + tb;
            uint32_t Ah[2][4], Al[2][4];
#pragma unroll
            for (int i = 0; i < 2; i++) {
                ldsm4(ab + (2 * mt + i) * 512 + aSw, Ah[i]);
                ldsm4(ab + 4096 + (2 * mt + i) * 512 + aSw, Al[i]);
            }
#pragma unroll
            for (int jj = 0; jj < 4; jj++) {
                uint32_t Bh4[4], Bl4[4];
                ldsm4t(bb + (8 * nt + 2 * jj) * 256, Bh4);
                ldsm4t(bb + 4096 + (8 * nt + 2 * jj) * 256, Bl4);
#pragma unroll
                for (int sj = 0; sj < 2; sj++) {
                    const uint32_t* Bh = Bh4 + 2 * sj;
                    const uint32_t* Bl = Bl4 + 2 * sj;
#pragma unroll
                    for (int i = 0; i < 2; i++) {
                        hmma(acc[i][2 * jj + sj], Ah[i], Bh);
                        hmma(acc[i][2 * jj + sj], Al[i], Bh);
                        hmma(acc[i][2 * jj + sj], Ah[i], Bl);
                    }
                }
            }
        }
        __syncthreads();
    }
    const int g = lane >> 2, c2 = (lane & 3) << 1;
#pragma unroll
    for (int j = 0; j < 8; j++) {
        const int n0 = NB * 128 + nt * 64 + j * 8 + c2;
        const float2 bxv = *(const float2*)(bx + n0);
        const float2 bhv = *(const float2*)(bh + n0);
        const float b0 = bxv.x + bhv.x, b1 = bxv.y + bhv.y;
#pragma unroll
        for (int i = 0; i < 2; i++) {
            const int m0 = MB * 128 + mt * 32 + i * 16 + g;
            *(float2*)(g_xg + (size_t)m0 * G4 + n0) =
                make_float2(acc[i][j][0] + b0, acc[i][j][1] + b1);
            *(float2*)(g_xg + (size_t)(m0 + 8) * G4 + n0) =
                make_float2(acc[i][j][2] + b0, acc[i][j][3] + b1);
        }
    }
}

// ---- Phase 2: persistent HMMA recurrence, per-producer flag gating ----------
__global__ void __launch_bounds__(256, 1) lstm_hmma_kernel(float* __restrict__ out)
{
    extern __shared__ unsigned char smc[];
    const uint32_t smb = (uint32_t)__cvta_generic_to_shared(smc);
    const int tid = threadIdx.x, lane = tid & 31, w = tid >> 5;
    const int r = lane & 15, hb = lane >> 4;

    {
        const unsigned char* src = g_W + (size_t)blockIdx.x * 131072;
#pragma unroll
        for (int cq = 0; cq < 32; cq++)
            cpa(smb + tid * 16 + cq * 4096, src + tid * 16 + cq * 4096);
        COMMIT();
        WAITG(0);
        __syncthreads();
    }
    uint32_t Ah[2][8][4], Al[2][8][4];
    {
        const uint32_t aSw = (uint32_t)(r * 32 + ((hb ^ ((r >> 2) & 1)) << 4));
#pragma unroll
        for (int mt = 0; mt < 2; mt++)
#pragma unroll
            for (int j = 0; j < 8; j++) {
                ldsm4(smb + mt * 32768 + (w * 8 + j) * 512 + aSw, Ah[mt][j]);
                ldsm4(smb + 65536 + mt * 32768 + (w * 8 + j) * 512 + aSw, Al[mt][j]);
            }
    }
    __syncthreads();

    float* Dp = (float*)(smc + DPOFF);
    const int cell = tid & 7, b = tid >> 3;
    const int n = blockIdx.x * 8 + cell;
    const uint32_t tb = (uint32_t)(r * 16 + hb * 256);
    float cs = 0.0f;

    // this warp's producer flag (k-cells [128w,128w+128) come from blocks [16w,16w+16))
    int* const myflag = &g_flag[((w << 4) + (lane & 15)) << 5];

    float xgv[4];
    {
        const float* xp = g_xg + ((size_t)b * TDIM) * G4 + n;
#pragma unroll
        for (int g2 = 0; g2 < 4; g2++) xgv[g2] = __ldg(xp + g2 * HDIM);
    }

    for (int t = 0; t < TDIM; t++) {
        // per-warp producer gate: wait until my 16 producers published h(t)
        for (;;) {
            const int v = ld_acquire(myflag);
            if (__all_sync(0xffffffffu, v >= t)) break;
        }

        const unsigned char* hsrc = g_hB[t & 1];
        // per-warp staging, 4 commit groups (hi0,hi1,lo0,lo1)
        {
            const uint32_t dh = smb + HBH + w * 8192 + lane * 16;
            const uint32_t dl = smb + HBL + w * 8192 + lane * 16;
            const unsigned char* sh = hsrc + w * 8192 + lane * 16;
            const unsigned char* sl = hsrc + 65536 + w * 8192 + lane * 16;
#pragma unroll
            for (int q = 0; q < 8; q++)  cpa(dh + q * 512, sh + q * 512);
            COMMIT();
#pragma unroll
            for (int q = 8; q < 16; q++) cpa(dh + q * 512, sh + q * 512);
            COMMIT();
#pragma unroll
            for (int q = 0; q < 8; q++)  cpa(dl + q * 512, sl + q * 512);
            COMMIT();
#pragma unroll
            for (int q = 8; q < 16; q++) cpa(dl + q * 512, sl + q * 512);
            COMMIT();
        }

        float acc[2][4][4];
#pragma unroll
        for (int mt = 0; mt < 2; mt++)
#pragma unroll
            for (int nt = 0; nt < 4; nt++)
#pragma unroll
                for (int q = 0; q < 4; q++) acc[mt][nt][q] = 0.0f;

#define CSTEP(BASE, J, THREE)                                                  \
        {                                                                      \
            uint32_t B01[4], B23[4];                                           \
            const uint32_t jb = smb + (BASE) + (w * 8 + (J)) * 1024 + tb;      \
            ldsm4t(jb, B01);                                                   \
            ldsm4t(jb + 512, B23);                                             \
            _Pragma("unroll")                                                  \
            for (int mt = 0; mt < 2; mt++) {                                   \
                hmma(acc[mt][0], Ah[mt][J], B01);                              \
                hmma(acc[mt][1], Ah[mt][J], B01 + 2);                          \
                hmma(acc[mt][2], Ah[mt][J], B23);                              \
                hmma(acc[mt][3], Ah[mt][J], B23 + 2);                          \
                if (THREE) {                                                   \
                    hmma(acc[mt][0], Al[mt][J], B01);                          \
                    hmma(acc[mt][1], Al[mt][J], B01 + 2);                      \
                    hmma(acc[mt][2], Al[mt][J], B23);                          \
                    hmma(acc[mt][3], Al[mt][J], B23 + 2);                      \
                }                                                              \
            }                                                                  \
        }

        WAITG(3); __syncwarp();
#pragma unroll
        for (int j = 0; j < 4; j++) CSTEP(HBH, j, 1)
        WAITG(2); __syncwarp();
#pragma unroll
        for (int j = 4; j < 8; j++) CSTEP(HBH, j, 1)
        WAITG(1); __syncwarp();
#pragma unroll
        for (int j = 0; j < 4; j++) CSTEP(HBL, j, 0)
        WAITG(0); __syncwarp();
#pragma unroll
        for (int j = 4; j < 8; j++) CSTEP(HBL, j, 0)

        {
            const int g = lane >> 2, c2 = (lane & 3) << 1;
            float* dpw = Dp + w * 1088;
#pragma unroll
            for (int mt = 0; mt < 2; mt++)
#pragma unroll
                for (int nt = 0; nt < 4; nt++) {
                    const int r0 = mt * 16 + g, c0 = nt * 8 + c2;
                    *(float2*)(dpw + r0 * 34 + c0) =
                        make_float2(acc[mt][nt][0], acc[mt][nt][1]);
                    *(float2*)(dpw + (r0 + 8) * 34 + c0) =
                        make_float2(acc[mt][nt][2], acc[mt][nt][3]);
                }
        }
        __syncthreads();     // sync1: all K-partials visible; implies all flags >= t

        float h_out;
        {
            float s0 = xgv[0], s1 = xgv[1], s2 = xgv[2], s3 = xgv[3];
#pragma unroll
            for (int w2 = 0; w2 < 8; w2++) {
                const float* dpw = Dp + w2 * 1088 + cell * 34 + b;
                s0 += dpw[0];
                s1 += dpw[8 * 34];
                s2 += dpw[16 * 34];
                s3 += dpw[24 * 34];
            }
            const float si = sigx(s0);
            const float sf = sigx(s1);
            const float so = sigx(s3);
            cs = sf * cs + si * tanhx(s2);
            h_out = so * tanhx(cs);

            unsigned short hh, hl; split_bf16(h_out, hh, hl);
            unsigned char* hd = g_hB[(t + 1) & 1];
            const uint32_t off = (uint32_t)((n >> 4) * 1024 + (b >> 3) * 256
                                 + (n & 15) * 16 + (b & 7) * 2);
            *(unsigned short*)(hd + off)         = hh;
            *(unsigned short*)(hd + 65536 + off) = hl;
        }

        __syncthreads();     // sync2: all h(t+1) tile stores done (CTA HB)
        if (tid == 0) st_release(&g_flag[blockIdx.x << 5], t + 1);

        // off the release path: fp32 output store + next xg prefetch
        out[((size_t)b * TDIM + t) * HDIM + n] = h_out;
        if (t + 1 < TDIM) {
            const float* xp = g_xg + ((size_t)b * TDIM + (t + 1)) * G4 + n;
#pragma unroll
            for (int g2 = 0; g2 < 4; g2++) xgv[g2] = __ldg(xp + g2 * HDIM);
        }
    }
}

// ---------------------------------------------------------------------------
extern "C" void kernel_launch(void* const* d_in, const int* in_sizes, int n_in,
                              void* d_out, int out_size)
{
    const float* x  = (const float*)d_in[0];
    const float* Wx = (const float*)d_in[1];
    const float* bx = (const float*)d_in[2];
    const float* Wh = (const float*)d_in[3];
    const float* bh = (const float*)d_in[4];
    float* out = (float*)d_out;
    (void)in_sizes; (void)n_in; (void)out_size;

    cudaFuncSetAttribute(lstm_hmma_kernel,
                         cudaFuncAttributeMaxDynamicSharedMemorySize, SMEM2);
    cudaFuncSetAttribute(gemm_hmma_kernel,
                         cudaFuncAttributeMaxDynamicSharedMemorySize, SMEM_G);

    prep_kernel<<<8192, 256>>>(Wh);
    prepA_kernel<<<16384, 256>>>(x);
    prepB_kernel<<<8192, 256>>>(Wx);

    dim3 ggrid(32, 128);
    gemm_hmma_kernel<<<ggrid, 256, SMEM_G>>>(bx, bh);

    lstm_hmma_kernel<<<NBLK, 256, SMEM2>>>(out);
}